// round 13
// baseline (speedup 1.0000x reference)
#include <cuda_runtime.h>
#include <math.h>
#include <stdint.h>

#define TOK 4096
#define HID 1024
#define FFN 4096
#define NE  8
#define NPART 64

#define BM 128
#define BN 128
#define BK 32
#define SROW 36                         // words per smem row (32 data + 4 pad)
#define STAGES 3
#define STG_W ((BM + BN) * SROW)        // 9216 words per stage
#define SMEM_BYTES (STAGES * STG_W * 4) // 110592

#define G1_NT (FFN / BN)                // 32
#define G1_MT (TOK / BM)                // 32
#define G2_NT (HID / BN)                // 8
#define G1_TILES (G1_NT * G1_MT * NE)   // 8192
#define G2_TILES (G2_NT * G1_MT * NE)   // 2048

// ---------------- device scratch (static; no allocation) ----------------
__device__ float g_probsum_part[NE * NPART];
__device__ int   g_counts_part[NE * NPART];
__device__ int   g_offsets[NE + 1];
__device__ int   g_cursor[NE];
__device__ int   g_perm[TOK];
__device__ int   g_expert[TOK];
__device__ float g_gate[TOK];
__device__ int   g_done[NE * G1_MT];    // gemm1 n-tile completion counters per (e, mtile)
// Activations stored tf32-pre-rounded (+BM pad rows for tile overreach)
__device__ float g_xg[(size_t)(TOK + BM) * HID];
__device__ float g_h[(size_t)(TOK + BM) * FFN];

// ---------------- helpers ----------------
__device__ __forceinline__ float gelu_exact(float v) {
    return 0.5f * v * (1.0f + erff(v * 0.70710678118654752f));
}
__device__ __forceinline__ uint32_t cvt_tf32(float f) {
    uint32_t u; asm("cvt.rna.tf32.f32 %0, %1;" : "=r"(u) : "f"(f)); return u;
}
__device__ __forceinline__ float rna_f(float f) {
    return __uint_as_float(cvt_tf32(f));
}
__device__ __forceinline__ void cp16(uint32_t saddr, const void* g) {
    asm volatile("cp.async.cg.shared.global [%0], [%1], 16;" :: "r"(saddr), "l"(g));
}
__device__ __forceinline__ void mma_tf32(float c[4], const uint32_t a[4], const uint32_t b[2]) {
    asm volatile("mma.sync.aligned.m16n8k8.row.col.f32.tf32.tf32.f32 "
        "{%0,%1,%2,%3}, {%4,%5,%6,%7}, {%8,%9}, {%0,%1,%2,%3};"
        : "+f"(c[0]), "+f"(c[1]), "+f"(c[2]), "+f"(c[3])
        : "r"(a[0]), "r"(a[1]), "r"(a[2]), "r"(a[3]), "r"(b[0]), "r"(b[1]));
}

// ---------------- router ----------------
__global__ __launch_bounds__(256) void router_kernel(const float* __restrict__ x,
                                                     const float* __restrict__ rw) {
    int t = blockIdx.x;
    __shared__ float xs[HID];
    __shared__ float lg[NE];
    const float4* x4 = (const float4*)(x + (size_t)t * HID);
    ((float4*)xs)[threadIdx.x] = x4[threadIdx.x];
    __syncthreads();

    int w = threadIdx.x >> 5, lane = threadIdx.x & 31;
    const float* rwe = rw + w * HID;
    float s = 0.f;
    #pragma unroll 8
    for (int i = lane; i < HID; i += 32) s += xs[i] * rwe[i];
    #pragma unroll
    for (int o = 16; o; o >>= 1) s += __shfl_xor_sync(0xffffffffu, s, o);
    if (lane == 0) lg[w] = s;
    __syncthreads();

    if (threadIdx.x == 0) {
        float mx = lg[0]; int idx = 0;
        #pragma unroll
        for (int e = 1; e < NE; e++) if (lg[e] > mx) { mx = lg[e]; idx = e; }
        float p[NE]; float den = 0.f;
        #pragma unroll
        for (int e = 0; e < NE; e++) { p[e] = expf(lg[e] - mx); den += p[e]; }
        float inv = 1.f / den;
        int part = t & (NPART - 1);
        #pragma unroll
        for (int e = 0; e < NE; e++) atomicAdd(&g_probsum_part[e * NPART + part], p[e] * inv);
        g_gate[t] = p[idx] * inv;
        g_expert[t] = idx;
        atomicAdd(&g_counts_part[idx * NPART + part], 1);
    }
}

// ---------------- prefix (re-zeroes accumulators + gemm dependency counters) ----------------
__global__ __launch_bounds__(256) void prefix_kernel(float* __restrict__ out, int out_size) {
    __shared__ float ps[NE];
    __shared__ int   cs[NE];
    int tid = threadIdx.x;
    if (tid < NE) {
        float s = 0.f; int c = 0;
        for (int p = 0; p < NPART; p++) {
            s += g_probsum_part[tid * NPART + p];
            c += g_counts_part[tid * NPART + p];
        }
        ps[tid] = s; cs[tid] = c;
    }
    __syncthreads();
    for (int i = tid; i < NE * NPART; i += 256) { g_probsum_part[i] = 0.f; g_counts_part[i] = 0; }
    for (int i = tid; i < NE * G1_MT; i += 256) g_done[i] = 0;
    if (tid == 0) {
        int run = 0; float aux = 0.f;
        for (int e = 0; e < NE; e++) {
            g_offsets[e] = run; g_cursor[e] = run;
            run += cs[e];
            aux += ps[e] * (float)cs[e];
        }
        g_offsets[NE] = run;
        aux *= 0.01f * (float)NE / ((float)TOK * (float)TOK);
        if (out_size > TOK * HID) out[TOK * HID] = aux;
    }
}

// ---------------- gather (stores tf32-pre-rounded activations) ----------------
__global__ __launch_bounds__(256) void gather_kernel(const float* __restrict__ x) {
    int t = blockIdx.x;
    __shared__ int slot_s;
    if (threadIdx.x == 0) {
        int e = g_expert[t];
        int slot = atomicAdd(&g_cursor[e], 1);
        g_perm[slot] = t;
        slot_s = slot;
    }
    __syncthreads();
    int slot = slot_s;
    float4 v = ((const float4*)(x + (size_t)t * HID))[threadIdx.x];
    float4 o; o.x = rna_f(v.x); o.y = rna_f(v.y); o.z = rna_f(v.z); o.w = rna_f(v.w);
    ((float4*)(g_xg + (size_t)slot * HID))[threadIdx.x] = o;
}

// ---------------- GEMM tile: 256 threads, 8 warps (2x4) of 64x32, dbl-buffered frags ----------------
template<int KDIM, bool IS_FC1>
__device__ __forceinline__ void gemm_tile(const float* __restrict__ W,
                                          const float* __restrict__ bias,
                                          float* __restrict__ outp,
                                          int e, int mt, int nt) {
    int off = g_offsets[e];
    int ne  = g_offsets[e + 1] - off;
    int m0  = mt * BM;
    if (m0 >= ne) return;
    int n0 = nt * BN;

    // gemm2 tiles wait for all 32 gemm1 n-tiles of this (e, mtile)
    if (!IS_FC1) {
        if (threadIdx.x == 0) {
            while (atomicAdd(&g_done[e * G1_MT + mt], 0) < G1_NT) __nanosleep(100);
        }
        __syncthreads();
        __threadfence();
    }

    const int NDIM = IS_FC1 ? FFN : HID;
    const float* A = (IS_FC1 ? g_xg : g_h) + (size_t)(off + m0) * KDIM;
    const float* B = W + (size_t)e * NDIM * KDIM + (size_t)n0 * KDIM;

    extern __shared__ float sm[];   // [STAGES][256 rows][SROW]; rows 0-127 = A, 128-255 = B
    uint32_t smBase = (uint32_t)__cvta_generic_to_shared(sm);

    int tid = threadIdx.x;
    int wid = tid >> 5, lane = tid & 31;

    // ---- producer mapping: 4 A-chunks (cp.async) + 4 B-chunks (LDG->cvt->STS) per thread ----
    int rowc[4], kqc[4];
    #pragma unroll
    for (int t = 0; t < 4; t++) { int c = tid + t * 256; rowc[t] = c >> 3; kqc[t] = (c & 7) * 4; }

    uint32_t aDst[4]; const float* aSrc[4];
    const float* bSrc[4]; float* bDst[4];
    #pragma unroll
    for (int t = 0; t < 4; t++) {
        aDst[t] = smBase + (rowc[t] * SROW + kqc[t]) * 4;
        aSrc[t] = A + (size_t)rowc[t] * KDIM + kqc[t];
        bSrc[t] = B + (size_t)rowc[t] * KDIM + kqc[t];
        bDst[t] = sm + (BM + rowc[t]) * SROW + kqc[t];
    }

    // ---- prologue: stages 0,1 ----
    #pragma unroll
    for (int s = 0; s < 2; s++) {
        #pragma unroll
        for (int t = 0; t < 4; t++) cp16(aDst[t] + s * STG_W * 4, aSrc[t] + s * BK);
        #pragma unroll
        for (int t = 0; t < 4; t++) {
            float4 q = *(const float4*)(bSrc[t] + s * BK);
            float4 o; o.x = rna_f(q.x); o.y = rna_f(q.y); o.z = rna_f(q.z); o.w = rna_f(q.w);
            *(float4*)(bDst[t] + s * STG_W) = o;
        }
        asm volatile("cp.async.commit_group;" ::: "memory");
    }

    // ---- consumer mapping: 8 warps, 2(m) x 4(n), warp tile 64x32 ----
    int wm = wid & 1;        // m offset wm*64
    int wn = wid >> 1;       // n offset wn*32
    int g  = lane >> 2;
    int t4 = lane & 3;

    float acc[4][4][4] = {};
    uint32_t af[2][4][4], bf[2][4][2];

    const int KT = KDIM / BK;
    int s = 0;
    for (int kt = 0; kt < KT; kt++) {
        asm volatile("cp.async.wait_group 1;" ::: "memory");
        __syncthreads();

        int nk = kt + 2;
        bool more = nk < KT;
        int ns = s + 2; if (ns >= STAGES) ns -= STAGES;
        float4 bq[4];
        if (more) {
            int ko = nk * BK;
            #pragma unroll
            for (int t = 0; t < 4; t++) cp16(aDst[t] + ns * STG_W * 4, aSrc[t] + ko);
            #pragma unroll
            for (int t = 0; t < 4; t++) bq[t] = *(const float4*)(bSrc[t] + ko);
        }
        asm volatile("cp.async.commit_group;" ::: "memory");

        const uint32_t* As = (const uint32_t*)(sm + s * STG_W);
        const uint32_t* Bs = As + BM * SROW;

        // preload slice 0 fragments
        #pragma unroll
        for (int i = 0; i < 4; i++) {
            int rm = wm * 64 + i * 16 + g;
            af[0][i][0] = As[rm * SROW + t4];
            af[0][i][1] = As[(rm + 8) * SROW + t4];
            af[0][i][2] = As[rm * SROW + t4 + 4];
            af[0][i][3] = As[(rm + 8) * SROW + t4 + 4];
        }
        #pragma unroll
        for (int j = 0; j < 4; j++) {
            int rn = wn * 32 + j * 8 + g;
            bf[0][j][0] = Bs[rn * SROW + t4];
            bf[0][j][1] = Bs[rn * SROW + t4 + 4];
        }

        #pragma unroll
        for (int ks = 0; ks < BK / 8; ks++) {
            int cur = ks & 1, nxt = cur ^ 1;
            if (ks + 1 < BK / 8) {
                int kb = (ks + 1) * 8;
                #pragma unroll
                for (int i = 0; i < 4; i++) {
                    int rm = wm * 64 + i * 16 + g;
                    af[nxt][i][0] = As[rm * SROW + kb + t4];
                    af[nxt][i][1] = As[(rm + 8) * SROW + kb + t4];
                    af[nxt][i][2] = As[rm * SROW + kb + t4 + 4];
                    af[nxt][i][3] = As[(rm + 8) * SROW + kb + t4 + 4];
                }
                #pragma unroll
                for (int j = 0; j < 4; j++) {
                    int rn = wn * 32 + j * 8 + g;
                    bf[nxt][j][0] = Bs[rn * SROW + kb + t4];
                    bf[nxt][j][1] = Bs[rn * SROW + kb + t4 + 4];
                }
            }
            #pragma unroll
            for (int i = 0; i < 4; i++)
                #pragma unroll
                for (int j = 0; j < 4; j++)
                    mma_tf32(acc[i][j], af[cur][i], bf[cur][j]);
        }

        // convert + store B for stage kt+2 (LDG latency hidden under the MMA block above)
        if (more) {
            #pragma unroll
            for (int t = 0; t < 4; t++) {
                float4 o; o.x = rna_f(bq[t].x); o.y = rna_f(bq[t].y); o.z = rna_f(bq[t].z); o.w = rna_f(bq[t].w);
                *(float4*)(bDst[t] + ns * STG_W) = o;
            }
        }
        s++; if (s == STAGES) s = 0;
    }

    // ---------------- epilogue ----------------
    #pragma unroll
    for (int i = 0; i < 4; i++) {
        int rml = wm * 64 + i * 16 + g;
        #pragma unroll
        for (int j = 0; j < 4; j++) {
            int col = n0 + wn * 32 + j * 8 + 2 * t4;
            if (IS_FC1) {
                float b0v = bias[(size_t)e * FFN + col];
                float b1v = bias[(size_t)e * FFN + col + 1];
                int m_ = m0 + rml;
                if (m_ < ne) {
                    float2 o;
                    o.x = rna_f(gelu_exact(acc[i][j][0] + b0v));
                    o.y = rna_f(gelu_exact(acc[i][j][1] + b1v));
                    *(float2*)&g_h[(size_t)(off + m_) * FFN + col] = o;
                }
                if (m_ + 8 < ne) {
                    float2 o;
                    o.x = rna_f(gelu_exact(acc[i][j][2] + b0v));
                    o.y = rna_f(gelu_exact(acc[i][j][3] + b1v));
                    *(float2*)&g_h[(size_t)(off + m_ + 8) * FFN + col] = o;
                }
            } else {
                float b0v = bias[(size_t)e * HID + col];
                float b1v = bias[(size_t)e * HID + col + 1];
                int m_ = m0 + rml;
                if (m_ < ne) {
                    int tok = g_perm[off + m_];
                    float gt = g_gate[tok];
                    float2 o;
                    o.x = (acc[i][j][0] + b0v) * gt;
                    o.y = (acc[i][j][1] + b1v) * gt;
                    *(float2*)&outp[(size_t)tok * HID + col] = o;
                }
                if (m_ + 8 < ne) {
                    int tok = g_perm[off + m_ + 8];
                    float gt = g_gate[tok];
                    float2 o;
                    o.x = (acc[i][j][2] + b0v) * gt;
                    o.y = (acc[i][j][3] + b1v) * gt;
                    *(float2*)&outp[(size_t)tok * HID + col] = o;
                }
            }
        }
    }

    // gemm1 tiles signal completion (release: all threads fence, then one arrives)
    if (IS_FC1) {
        __threadfence();
        __syncthreads();
        if (threadIdx.x == 0) atomicAdd(&g_done[e * G1_MT + mt], 1);
    }
}

// ---------------- fused gemm1+gemm2 launch ----------------
__global__ __launch_bounds__(256, 1) void moe_gemm_fused(const float* __restrict__ fc1_w,
                                                         const float* __restrict__ fc1_b,
                                                         const float* __restrict__ fc2_w,
                                                         const float* __restrict__ fc2_b,
                                                         float* __restrict__ outp) {
    int bid = blockIdx.x;
    if (bid < G1_TILES) {
        int e  = bid >> 10;              // / (G1_NT * G1_MT)
        int r  = bid & 1023;
        int mt = r >> 5;
        int nt = r & 31;
        gemm_tile<HID, true>(fc1_w, fc1_b, nullptr, e, mt, nt);
    } else {
        int b2 = bid - G1_TILES;
        int e  = b2 >> 8;                // / (G2_NT * G1_MT)
        int r  = b2 & 255;
        int mt = r >> 3;
        int nt = r & 7;
        gemm_tile<FFN, false>(fc2_w, fc2_b, outp, e, mt, nt);
    }
}

// ---------------- launch ----------------
extern "C" void kernel_launch(void* const* d_in, const int* in_sizes, int n_in,
                              void* d_out, int out_size) {
    const float* x        = (const float*)d_in[0];
    const float* router_w = (const float*)d_in[1];
    const float* fc1_w    = (const float*)d_in[2];
    const float* fc1_b    = (const float*)d_in[3];
    const float* fc2_w    = (const float*)d_in[4];
    const float* fc2_b    = (const float*)d_in[5];
    float* out = (float*)d_out;

    cudaFuncSetAttribute(moe_gemm_fused, cudaFuncAttributeMaxDynamicSharedMemorySize, SMEM_BYTES);

    router_kernel<<<TOK, 256>>>(x, router_w);
    prefix_kernel<<<1, 256>>>(out, out_size);
    gather_kernel<<<TOK, 256>>>(x);

    moe_gemm_fused<<<G1_TILES + G2_TILES, 256, SMEM_BYTES>>>(fc1_w, fc1_b, fc2_w, fc2_b, out);
}

// round 14
// speedup vs baseline: 1.1539x; 1.1539x over previous
#include <cuda_runtime.h>
#include <math.h>
#include <stdint.h>

#define TOK 4096
#define HID 1024
#define FFN 4096
#define NE  8
#define NPART 64

#define BM 128
#define BN 128
#define BK 32
#define SROW 36                         // words per smem row (32 data + 4 pad)
#define STAGES 3
#define STG_W ((BM + BN) * SROW)        // 9216 words per stage
#define SMEM_BYTES (STAGES * STG_W * 4) // 110592

#define G1_NT (FFN / BN)                // 32
#define G1_MT (TOK / BM)                // 32
#define G2_NT (HID / BN)                // 8
#define G1_TILES (G1_NT * G1_MT * NE)   // 8192
#define G2_TILES (G2_NT * G1_MT * NE)   // 2048

// ---------------- device scratch (static; no allocation) ----------------
__device__ float g_probsum_part[NE * NPART];
__device__ int   g_counts_part[NE * NPART];
__device__ int   g_offsets[NE + 1];
__device__ int   g_cursor[NE];
__device__ int   g_perm[TOK];
__device__ int   g_expert[TOK];
__device__ float g_gate[TOK];
__device__ int   g_gath[NE * G1_MT];    // gathered-row counters per (e, mtile)
__device__ int   g_done[NE * G1_MT];    // gemm1 n-tile completion counters per (e, mtile)
// Activations stored tf32-pre-rounded (+BM pad rows for tile overreach)
__device__ float g_xg[(size_t)(TOK + BM) * HID];
__device__ float g_h[(size_t)(TOK + BM) * FFN];

// ---------------- helpers ----------------
__device__ __forceinline__ float gelu_exact(float v) {
    return 0.5f * v * (1.0f + erff(v * 0.70710678118654752f));
}
__device__ __forceinline__ uint32_t cvt_tf32(float f) {
    uint32_t u; asm("cvt.rna.tf32.f32 %0, %1;" : "=r"(u) : "f"(f)); return u;
}
__device__ __forceinline__ float rna_f(float f) {
    return __uint_as_float(cvt_tf32(f));
}
__device__ __forceinline__ void cp16(uint32_t saddr, const void* g) {
    asm volatile("cp.async.cg.shared.global [%0], [%1], 16;" :: "r"(saddr), "l"(g));
}
__device__ __forceinline__ void mma_tf32(float c[4], const uint32_t a[4], const uint32_t b[2]) {
    asm volatile("mma.sync.aligned.m16n8k8.row.col.f32.tf32.tf32.f32 "
        "{%0,%1,%2,%3}, {%4,%5,%6,%7}, {%8,%9}, {%0,%1,%2,%3};"
        : "+f"(c[0]), "+f"(c[1]), "+f"(c[2]), "+f"(c[3])
        : "r"(a[0]), "r"(a[1]), "r"(a[2]), "r"(a[3]), "r"(b[0]), "r"(b[1]));
}

// ---------------- router ----------------
__global__ __launch_bounds__(256) void router_kernel(const float* __restrict__ x,
                                                     const float* __restrict__ rw) {
    int t = blockIdx.x;
    __shared__ float xs[HID];
    __shared__ float lg[NE];
    const float4* x4 = (const float4*)(x + (size_t)t * HID);
    ((float4*)xs)[threadIdx.x] = x4[threadIdx.x];
    __syncthreads();

    int w = threadIdx.x >> 5, lane = threadIdx.x & 31;
    const float* rwe = rw + w * HID;
    float s = 0.f;
    #pragma unroll 8
    for (int i = lane; i < HID; i += 32) s += xs[i] * rwe[i];
    #pragma unroll
    for (int o = 16; o; o >>= 1) s += __shfl_xor_sync(0xffffffffu, s, o);
    if (lane == 0) lg[w] = s;
    __syncthreads();

    if (threadIdx.x == 0) {
        float mx = lg[0]; int idx = 0;
        #pragma unroll
        for (int e = 1; e < NE; e++) if (lg[e] > mx) { mx = lg[e]; idx = e; }
        float p[NE]; float den = 0.f;
        #pragma unroll
        for (int e = 0; e < NE; e++) { p[e] = expf(lg[e] - mx); den += p[e]; }
        float inv = 1.f / den;
        int part = t & (NPART - 1);
        #pragma unroll
        for (int e = 0; e < NE; e++) atomicAdd(&g_probsum_part[e * NPART + part], p[e] * inv);
        g_gate[t] = p[idx] * inv;
        g_expert[t] = idx;
        atomicAdd(&g_counts_part[idx * NPART + part], 1);
    }
}

// ---------------- prefix (re-zeroes accumulators + dependency counters) ----------------
__global__ __launch_bounds__(256) void prefix_kernel(float* __restrict__ out, int out_size) {
    __shared__ float ps[NE];
    __shared__ int   cs[NE];
    int tid = threadIdx.x;
    if (tid < NE) {
        float s = 0.f; int c = 0;
        for (int p = 0; p < NPART; p++) {
            s += g_probsum_part[tid * NPART + p];
            c += g_counts_part[tid * NPART + p];
        }
        ps[tid] = s; cs[tid] = c;
    }
    __syncthreads();
    for (int i = tid; i < NE * NPART; i += 256) { g_probsum_part[i] = 0.f; g_counts_part[i] = 0; }
    for (int i = tid; i < NE * G1_MT; i += 256) { g_done[i] = 0; g_gath[i] = 0; }
    if (tid == 0) {
        int run = 0; float aux = 0.f;
        for (int e = 0; e < NE; e++) {
            g_offsets[e] = run; g_cursor[e] = run;
            run += cs[e];
            aux += ps[e] * (float)cs[e];
        }
        g_offsets[NE] = run;
        aux *= 0.01f * (float)NE / ((float)TOK * (float)TOK);
        if (out_size > TOK * HID) out[TOK * HID] = aux;
    }
}

// ---------------- GEMM tile (R12-proven body: 128 thr, 4 warps 2x2 of 64x64) ----------------
template<int KDIM, bool IS_FC1>
__device__ __forceinline__ void gemm_tile(const float* __restrict__ W,
                                          const float* __restrict__ bias,
                                          float* __restrict__ outp,
                                          int e, int mt, int nt) {
    int off = g_offsets[e];
    int ne  = g_offsets[e + 1] - off;
    int m0  = mt * BM;
    if (m0 >= ne) return;
    int n0 = nt * BN;

    // dependency acquire
    if (IS_FC1) {
        // wait until this tile's A rows are gathered
        int target = ne - m0; if (target > BM) target = BM;
        if (threadIdx.x == 0) {
            while (atomicAdd(&g_gath[e * G1_MT + mt], 0) < target) __nanosleep(100);
        }
        __syncthreads();
        __threadfence();
    } else {
        // wait for all 32 gemm1 n-tiles of this (e, mtile)
        if (threadIdx.x == 0) {
            while (atomicAdd(&g_done[e * G1_MT + mt], 0) < G1_NT) __nanosleep(100);
        }
        __syncthreads();
        __threadfence();
    }

    const int NDIM = IS_FC1 ? FFN : HID;
    const float* A = (IS_FC1 ? g_xg : g_h) + (size_t)(off + m0) * KDIM;
    const float* B = W + (size_t)e * NDIM * KDIM + (size_t)n0 * KDIM;

    extern __shared__ float sm[];   // [STAGES][256 rows][SROW]; rows 0-127 = A, 128-255 = B
    uint32_t smBase = (uint32_t)__cvta_generic_to_shared(sm);

    int tid = threadIdx.x;
    int wid = tid >> 5, lane = tid & 31;

    // ---- producer mapping: 8 A-chunks (cp.async) + 8 B-chunks (LDG->cvt->STS) per thread ----
    int rowc[8], kqc[8];
    #pragma unroll
    for (int t = 0; t < 8; t++) { int c = tid + t * 128; rowc[t] = c >> 3; kqc[t] = (c & 7) * 4; }

    uint32_t aDst[8]; const float* aSrc[8];
    const float* bSrc[8]; float* bDst[8];
    #pragma unroll
    for (int t = 0; t < 8; t++) {
        aDst[t] = smBase + (rowc[t] * SROW + kqc[t]) * 4;
        aSrc[t] = A + (size_t)rowc[t] * KDIM + kqc[t];
        bSrc[t] = B + (size_t)rowc[t] * KDIM + kqc[t];
        bDst[t] = sm + (BM + rowc[t]) * SROW + kqc[t];
    }

    // ---- prologue: stages 0,1 ----
    #pragma unroll
    for (int s = 0; s < 2; s++) {
        #pragma unroll
        for (int t = 0; t < 8; t++) cp16(aDst[t] + s * STG_W * 4, aSrc[t] + s * BK);
        #pragma unroll
        for (int t = 0; t < 8; t++) {
            float4 q = *(const float4*)(bSrc[t] + s * BK);
            float4 o; o.x = rna_f(q.x); o.y = rna_f(q.y); o.z = rna_f(q.z); o.w = rna_f(q.w);
            *(float4*)(bDst[t] + s * STG_W) = o;
        }
        asm volatile("cp.async.commit_group;" ::: "memory");
    }

    // ---- consumer mapping: 4 warps, 2x2, warp tile 64x64 ----
    int wm = wid & 1;
    int wn = wid >> 1;
    int g  = lane >> 2;
    int t4 = lane & 3;

    float acc[4][8][4] = {};

    const int KT = KDIM / BK;
    int s = 0;
    for (int kt = 0; kt < KT; kt++) {
        asm volatile("cp.async.wait_group 1;" ::: "memory");
        __syncthreads();

        int nk = kt + 2;
        bool more = nk < KT;
        int ns = s + 2; if (ns >= STAGES) ns -= STAGES;
        float4 bq[8];
        if (more) {
            int ko = nk * BK;
            #pragma unroll
            for (int t = 0; t < 8; t++) cp16(aDst[t] + ns * STG_W * 4, aSrc[t] + ko);
            #pragma unroll
            for (int t = 0; t < 8; t++) bq[t] = *(const float4*)(bSrc[t] + ko);
        }
        asm volatile("cp.async.commit_group;" ::: "memory");

        const uint32_t* As = (const uint32_t*)(sm + s * STG_W);
        const uint32_t* Bs = As + BM * SROW;
        #pragma unroll
        for (int ks = 0; ks < BK / 8; ks++) {
            int kb = ks * 8;
            uint32_t a[4][4];
            #pragma unroll
            for (int i = 0; i < 4; i++) {
                int rm = wm * 64 + i * 16 + g;
                a[i][0] = As[rm * SROW + kb + t4];
                a[i][1] = As[(rm + 8) * SROW + kb + t4];
                a[i][2] = As[rm * SROW + kb + t4 + 4];
                a[i][3] = As[(rm + 8) * SROW + kb + t4 + 4];
            }
            uint32_t b[8][2];
            #pragma unroll
            for (int j = 0; j < 8; j++) {
                int rn = wn * 64 + j * 8 + g;
                b[j][0] = Bs[rn * SROW + kb + t4];
                b[j][1] = Bs[rn * SROW + kb + t4 + 4];
            }
            #pragma unroll
            for (int i = 0; i < 4; i++)
                #pragma unroll
                for (int j = 0; j < 8; j++)
                    mma_tf32(acc[i][j], a[i], b[j]);
        }

        if (more) {
            #pragma unroll
            for (int t = 0; t < 8; t++) {
                float4 o; o.x = rna_f(bq[t].x); o.y = rna_f(bq[t].y); o.z = rna_f(bq[t].z); o.w = rna_f(bq[t].w);
                *(float4*)(bDst[t] + ns * STG_W) = o;
            }
        }
        s++; if (s == STAGES) s = 0;
    }

    // ---------------- epilogue ----------------
    #pragma unroll
    for (int i = 0; i < 4; i++) {
        int rml = wm * 64 + i * 16 + g;
        #pragma unroll
        for (int j = 0; j < 8; j++) {
            int col = n0 + wn * 64 + j * 8 + 2 * t4;
            if (IS_FC1) {
                float b0v = bias[(size_t)e * FFN + col];
                float b1v = bias[(size_t)e * FFN + col + 1];
                int m_ = m0 + rml;
                if (m_ < ne) {
                    float2 o;
                    o.x = rna_f(gelu_exact(acc[i][j][0] + b0v));
                    o.y = rna_f(gelu_exact(acc[i][j][1] + b1v));
                    *(float2*)&g_h[(size_t)(off + m_) * FFN + col] = o;
                }
                if (m_ + 8 < ne) {
                    float2 o;
                    o.x = rna_f(gelu_exact(acc[i][j][2] + b0v));
                    o.y = rna_f(gelu_exact(acc[i][j][3] + b1v));
                    *(float2*)&g_h[(size_t)(off + m_ + 8) * FFN + col] = o;
                }
            } else {
                float b0v = bias[(size_t)e * HID + col];
                float b1v = bias[(size_t)e * HID + col + 1];
                int m_ = m0 + rml;
                if (m_ < ne) {
                    int tok = g_perm[off + m_];
                    float gt = g_gate[tok];
                    float2 o;
                    o.x = (acc[i][j][0] + b0v) * gt;
                    o.y = (acc[i][j][1] + b1v) * gt;
                    *(float2*)&outp[(size_t)tok * HID + col] = o;
                }
                if (m_ + 8 < ne) {
                    int tok = g_perm[off + m_ + 8];
                    float gt = g_gate[tok];
                    float2 o;
                    o.x = (acc[i][j][2] + b0v) * gt;
                    o.y = (acc[i][j][3] + b1v) * gt;
                    *(float2*)&outp[(size_t)tok * HID + col] = o;
                }
            }
        }
    }

    // gemm1 tiles signal completion (release)
    if (IS_FC1) {
        __threadfence();
        __syncthreads();
        if (threadIdx.x == 0) atomicAdd(&g_done[e * G1_MT + mt], 1);
    }
}

// ---------------- gather block (inside fused kernel, 128 threads) ----------------
__device__ __forceinline__ void gather_block(const float* __restrict__ x, int t) {
    __shared__ int slot_s;
    if (threadIdx.x == 0) {
        int e = g_expert[t];
        int slot = atomicAdd(&g_cursor[e], 1);
        g_perm[slot] = t;
        slot_s = slot;
    }
    __syncthreads();
    int slot = slot_s;
    const float4* src = (const float4*)(x + (size_t)t * HID);
    float4* dst = (float4*)(g_xg + (size_t)slot * HID);
    #pragma unroll
    for (int k = 0; k < 2; k++) {
        int i = threadIdx.x + k * 128;
        float4 v = src[i];
        float4 o; o.x = rna_f(v.x); o.y = rna_f(v.y); o.z = rna_f(v.z); o.w = rna_f(v.w);
        dst[i] = o;
    }
    __threadfence();
    __syncthreads();
    if (threadIdx.x == 0) {
        int e = g_expert[t];
        int mt = (slot - g_offsets[e]) >> 7;     // /BM
        atomicAdd(&g_gath[e * G1_MT + mt], 1);
    }
}

// ---------------- fused gather + gemm1 + gemm2 ----------------
__global__ __launch_bounds__(128, 2) void moe_fused(const float* __restrict__ x,
                                                    const float* __restrict__ fc1_w,
                                                    const float* __restrict__ fc1_b,
                                                    const float* __restrict__ fc2_w,
                                                    const float* __restrict__ fc2_b,
                                                    float* __restrict__ outp) {
    int bid = blockIdx.x;
    if (bid < TOK) {
        gather_block(x, bid);
    } else if (bid < TOK + G1_TILES) {
        int b1 = bid - TOK;
        int e  = b1 >> 10;
        int r  = b1 & 1023;
        int mt = r >> 5;
        int nt = r & 31;
        gemm_tile<HID, true>(fc1_w, fc1_b, nullptr, e, mt, nt);
    } else {
        int b2 = bid - TOK - G1_TILES;
        int e  = b2 >> 8;
        int r  = b2 & 255;
        int mt = r >> 3;
        int nt = r & 7;
        gemm_tile<FFN, false>(fc2_w, fc2_b, outp, e, mt, nt);
    }
}

// ---------------- launch ----------------
extern "C" void kernel_launch(void* const* d_in, const int* in_sizes, int n_in,
                              void* d_out, int out_size) {
    const float* x        = (const float*)d_in[0];
    const float* router_w = (const float*)d_in[1];
    const float* fc1_w    = (const float*)d_in[2];
    const float* fc1_b    = (const float*)d_in[3];
    const float* fc2_w    = (const float*)d_in[4];
    const float* fc2_b    = (const float*)d_in[5];
    float* out = (float*)d_out;

    cudaFuncSetAttribute(moe_fused, cudaFuncAttributeMaxDynamicSharedMemorySize, SMEM_BYTES);

    router_kernel<<<TOK, 256>>>(x, router_w);
    prefix_kernel<<<1, 256>>>(out, out_size);
    moe_fused<<<TOK + G1_TILES + G2_TILES, 128, SMEM_BYTES>>>(x, fc1_w, fc1_b, fc2_w, fc2_b, out);
}

// round 15
// speedup vs baseline: 1.2058x; 1.0450x over previous
#include <cuda_runtime.h>
#include <math.h>
#include <stdint.h>

#define TOK 4096
#define HID 1024
#define FFN 4096
#define NE  8
#define NPART 64

#define BM 128
#define BN 128
#define BK 32
#define SROW 36                         // words per smem row (32 data + 4 pad)
#define STAGES 3
#define STG_W ((BM + BN) * SROW)        // 9216 words per stage
#define SMEM_BYTES (STAGES * STG_W * 4) // 110592

#define G1_NT (FFN / BN)                // 32
#define G1_MT (TOK / BM)                // 32
#define G2_NT (HID / BN)                // 8
#define G1_TILES (G1_NT * G1_MT * NE)   // 8192
#define G2_TILES (G2_NT * G1_MT * NE)   // 2048

// ---------------- device scratch (static; no allocation) ----------------
__device__ float g_probsum_part[NE * NPART];
__device__ int   g_counts_part[NE * NPART];
__device__ int   g_offsets[NE + 1];
__device__ int   g_cursor[NE];
__device__ int   g_perm[TOK];
__device__ int   g_expert[TOK];
__device__ float g_gate[TOK];
__device__ int   g_done[NE * G1_MT];    // gemm1 n-tile completion counters per (e, mtile)
// Activations stored tf32-pre-rounded (+BM pad rows for tile overreach)
__device__ float g_xg[(size_t)(TOK + BM) * HID];
__device__ float g_h[(size_t)(TOK + BM) * FFN];

// ---------------- helpers ----------------
__device__ __forceinline__ float gelu_exact(float v) {
    return 0.5f * v * (1.0f + erff(v * 0.70710678118654752f));
}
__device__ __forceinline__ uint32_t cvt_tf32(float f) {
    uint32_t u; asm("cvt.rna.tf32.f32 %0, %1;" : "=r"(u) : "f"(f)); return u;
}
__device__ __forceinline__ float rna_f(float f) {
    return __uint_as_float(cvt_tf32(f));
}
__device__ __forceinline__ void cp16(uint32_t saddr, const void* g) {
    asm volatile("cp.async.cg.shared.global [%0], [%1], 16;" :: "r"(saddr), "l"(g));
}
__device__ __forceinline__ void mma_tf32(float c[4], const uint32_t a[4], const uint32_t b[2]) {
    asm volatile("mma.sync.aligned.m16n8k8.row.col.f32.tf32.tf32.f32 "
        "{%0,%1,%2,%3}, {%4,%5,%6,%7}, {%8,%9}, {%0,%1,%2,%3};"
        : "+f"(c[0]), "+f"(c[1]), "+f"(c[2]), "+f"(c[3])
        : "r"(a[0]), "r"(a[1]), "r"(a[2]), "r"(a[3]), "r"(b[0]), "r"(b[1]));
}

// ---------------- router: warp-per-token, x read once, rw staged in smem ----------------
__global__ __launch_bounds__(256) void router_kernel(const float* __restrict__ x,
                                                     const float* __restrict__ rw) {
    __shared__ float4 rws[NE * 256];    // 8 experts x 1024 floats = 32KB
    int tid = threadIdx.x;
    #pragma unroll
    for (int i = 0; i < 8; i++) rws[tid + i * 256] = ((const float4*)rw)[tid + i * 256];
    __syncthreads();

    int wid = tid >> 5, lane = tid & 31;
    int t = blockIdx.x * 8 + wid;

    // load x row into registers (one coalesced pass)
    float4 xr[8];
    const float4* x4 = (const float4*)(x + (size_t)t * HID);
    #pragma unroll
    for (int k = 0; k < 8; k++) xr[k] = x4[k * 32 + lane];

    float lg[NE];
    #pragma unroll
    for (int e = 0; e < NE; e++) {
        float s = 0.f;
        #pragma unroll
        for (int k = 0; k < 8; k++) {
            float4 w = rws[e * 256 + k * 32 + lane];
            s += xr[k].x * w.x + xr[k].y * w.y + xr[k].z * w.z + xr[k].w * w.w;
        }
        #pragma unroll
        for (int o = 16; o; o >>= 1) s += __shfl_xor_sync(0xffffffffu, s, o);
        lg[e] = s;
    }

    if (lane == 0) {
        float mx = lg[0]; int idx = 0;
        #pragma unroll
        for (int e = 1; e < NE; e++) if (lg[e] > mx) { mx = lg[e]; idx = e; }
        float p[NE]; float den = 0.f;
        #pragma unroll
        for (int e = 0; e < NE; e++) { p[e] = expf(lg[e] - mx); den += p[e]; }
        float inv = 1.f / den;
        int part = t & (NPART - 1);
        #pragma unroll
        for (int e = 0; e < NE; e++) atomicAdd(&g_probsum_part[e * NPART + part], p[e] * inv);
        g_gate[t] = p[idx] * inv;
        g_expert[t] = idx;
        atomicAdd(&g_counts_part[idx * NPART + part], 1);
    }
}

// ---------------- prefix (re-zeroes accumulators + gemm dependency counters) ----------------
__global__ __launch_bounds__(256) void prefix_kernel(float* __restrict__ out, int out_size) {
    __shared__ float ps[NE];
    __shared__ int   cs[NE];
    int tid = threadIdx.x;
    if (tid < NE) {
        float s = 0.f; int c = 0;
        for (int p = 0; p < NPART; p++) {
            s += g_probsum_part[tid * NPART + p];
            c += g_counts_part[tid * NPART + p];
        }
        ps[tid] = s; cs[tid] = c;
    }
    __syncthreads();
    for (int i = tid; i < NE * NPART; i += 256) { g_probsum_part[i] = 0.f; g_counts_part[i] = 0; }
    for (int i = tid; i < NE * G1_MT; i += 256) g_done[i] = 0;
    if (tid == 0) {
        int run = 0; float aux = 0.f;
        for (int e = 0; e < NE; e++) {
            g_offsets[e] = run; g_cursor[e] = run;
            run += cs[e];
            aux += ps[e] * (float)cs[e];
        }
        g_offsets[NE] = run;
        aux *= 0.01f * (float)NE / ((float)TOK * (float)TOK);
        if (out_size > TOK * HID) out[TOK * HID] = aux;
    }
}

// ---------------- gather (stores tf32-pre-rounded activations) ----------------
__global__ __launch_bounds__(256) void gather_kernel(const float* __restrict__ x) {
    int t = blockIdx.x;
    __shared__ int slot_s;
    if (threadIdx.x == 0) {
        int e = g_expert[t];
        int slot = atomicAdd(&g_cursor[e], 1);
        g_perm[slot] = t;
        slot_s = slot;
    }
    __syncthreads();
    int slot = slot_s;
    float4 v = ((const float4*)(x + (size_t)t * HID))[threadIdx.x];
    float4 o; o.x = rna_f(v.x); o.y = rna_f(v.y); o.z = rna_f(v.z); o.w = rna_f(v.w);
    ((float4*)(g_xg + (size_t)slot * HID))[threadIdx.x] = o;
}

// ---------------- GEMM tile (R12-proven body: 128 thr, 4 warps 2x2 of 64x64) ----------------
template<int KDIM, bool IS_FC1>
__device__ __forceinline__ void gemm_tile(const float* __restrict__ W,
                                          const float* __restrict__ bias,
                                          float* __restrict__ outp,
                                          int e, int mt, int nt) {
    int off = g_offsets[e];
    int ne  = g_offsets[e + 1] - off;
    int m0  = mt * BM;
    if (m0 >= ne) return;
    int n0 = nt * BN;

    // gemm2 tiles wait for all 32 gemm1 n-tiles of this (e, mtile)
    if (!IS_FC1) {
        if (threadIdx.x == 0) {
            while (atomicAdd(&g_done[e * G1_MT + mt], 0) < G1_NT) __nanosleep(100);
        }
        __syncthreads();
        __threadfence();
    }

    const int NDIM = IS_FC1 ? FFN : HID;
    const float* A = (IS_FC1 ? g_xg : g_h) + (size_t)(off + m0) * KDIM;
    const float* B = W + (size_t)e * NDIM * KDIM + (size_t)n0 * KDIM;

    extern __shared__ float sm[];   // [STAGES][256 rows][SROW]; rows 0-127 = A, 128-255 = B
    uint32_t smBase = (uint32_t)__cvta_generic_to_shared(sm);

    int tid = threadIdx.x;
    int wid = tid >> 5, lane = tid & 31;

    // ---- producer mapping: 8 A-chunks (cp.async) + 8 B-chunks (LDG->cvt->STS) per thread ----
    int rowc[8], kqc[8];
    #pragma unroll
    for (int t = 0; t < 8; t++) { int c = tid + t * 128; rowc[t] = c >> 3; kqc[t] = (c & 7) * 4; }

    uint32_t aDst[8]; const float* aSrc[8];
    const float* bSrc[8]; float* bDst[8];
    #pragma unroll
    for (int t = 0; t < 8; t++) {
        aDst[t] = smBase + (rowc[t] * SROW + kqc[t]) * 4;
        aSrc[t] = A + (size_t)rowc[t] * KDIM + kqc[t];
        bSrc[t] = B + (size_t)rowc[t] * KDIM + kqc[t];
        bDst[t] = sm + (BM + rowc[t]) * SROW + kqc[t];
    }

    // ---- prologue: stages 0,1 ----
    #pragma unroll
    for (int s = 0; s < 2; s++) {
        #pragma unroll
        for (int t = 0; t < 8; t++) cp16(aDst[t] + s * STG_W * 4, aSrc[t] + s * BK);
        #pragma unroll
        for (int t = 0; t < 8; t++) {
            float4 q = *(const float4*)(bSrc[t] + s * BK);
            float4 o; o.x = rna_f(q.x); o.y = rna_f(q.y); o.z = rna_f(q.z); o.w = rna_f(q.w);
            *(float4*)(bDst[t] + s * STG_W) = o;
        }
        asm volatile("cp.async.commit_group;" ::: "memory");
    }

    // ---- consumer mapping: 4 warps, 2x2, warp tile 64x64 ----
    int wm = wid & 1;
    int wn = wid >> 1;
    int g  = lane >> 2;
    int t4 = lane & 3;

    float acc[4][8][4] = {};

    const int KT = KDIM / BK;
    int s = 0;
    for (int kt = 0; kt < KT; kt++) {
        asm volatile("cp.async.wait_group 1;" ::: "memory");
        __syncthreads();

        int nk = kt + 2;
        bool more = nk < KT;
        int ns = s + 2; if (ns >= STAGES) ns -= STAGES;
        float4 bq[8];
        if (more) {
            int ko = nk * BK;
            #pragma unroll
            for (int t = 0; t < 8; t++) cp16(aDst[t] + ns * STG_W * 4, aSrc[t] + ko);
            #pragma unroll
            for (int t = 0; t < 8; t++) bq[t] = *(const float4*)(bSrc[t] + ko);
        }
        asm volatile("cp.async.commit_group;" ::: "memory");

        const uint32_t* As = (const uint32_t*)(sm + s * STG_W);
        const uint32_t* Bs = As + BM * SROW;
        #pragma unroll
        for (int ks = 0; ks < BK / 8; ks++) {
            int kb = ks * 8;
            uint32_t a[4][4];
            #pragma unroll
            for (int i = 0; i < 4; i++) {
                int rm = wm * 64 + i * 16 + g;
                a[i][0] = As[rm * SROW + kb + t4];
                a[i][1] = As[(rm + 8) * SROW + kb + t4];
                a[i][2] = As[rm * SROW + kb + t4 + 4];
                a[i][3] = As[(rm + 8) * SROW + kb + t4 + 4];
            }
            uint32_t b[8][2];
            #pragma unroll
            for (int j = 0; j < 8; j++) {
                int rn = wn * 64 + j * 8 + g;
                b[j][0] = Bs[rn * SROW + kb + t4];
                b[j][1] = Bs[rn * SROW + kb + t4 + 4];
            }
            #pragma unroll
            for (int i = 0; i < 4; i++)
                #pragma unroll
                for (int j = 0; j < 8; j++)
                    mma_tf32(acc[i][j], a[i], b[j]);
        }

        if (more) {
            #pragma unroll
            for (int t = 0; t < 8; t++) {
                float4 o; o.x = rna_f(bq[t].x); o.y = rna_f(bq[t].y); o.z = rna_f(bq[t].z); o.w = rna_f(bq[t].w);
                *(float4*)(bDst[t] + ns * STG_W) = o;
            }
        }
        s++; if (s == STAGES) s = 0;
    }

    // ---------------- epilogue ----------------
    #pragma unroll
    for (int i = 0; i < 4; i++) {
        int rml = wm * 64 + i * 16 + g;
        #pragma unroll
        for (int j = 0; j < 8; j++) {
            int col = n0 + wn * 64 + j * 8 + 2 * t4;
            if (IS_FC1) {
                float b0v = bias[(size_t)e * FFN + col];
                float b1v = bias[(size_t)e * FFN + col + 1];
                int m_ = m0 + rml;
                if (m_ < ne) {
                    float2 o;
                    o.x = rna_f(gelu_exact(acc[i][j][0] + b0v));
                    o.y = rna_f(gelu_exact(acc[i][j][1] + b1v));
                    *(float2*)&g_h[(size_t)(off + m_) * FFN + col] = o;
                }
                if (m_ + 8 < ne) {
                    float2 o;
                    o.x = rna_f(gelu_exact(acc[i][j][2] + b0v));
                    o.y = rna_f(gelu_exact(acc[i][j][3] + b1v));
                    *(float2*)&g_h[(size_t)(off + m_ + 8) * FFN + col] = o;
                }
            } else {
                float b0v = bias[(size_t)e * HID + col];
                float b1v = bias[(size_t)e * HID + col + 1];
                int m_ = m0 + rml;
                if (m_ < ne) {
                    int tok = g_perm[off + m_];
                    float gt = g_gate[tok];
                    float2 o;
                    o.x = (acc[i][j][0] + b0v) * gt;
                    o.y = (acc[i][j][1] + b1v) * gt;
                    *(float2*)&outp[(size_t)tok * HID + col] = o;
                }
                if (m_ + 8 < ne) {
                    int tok = g_perm[off + m_ + 8];
                    float gt = g_gate[tok];
                    float2 o;
                    o.x = (acc[i][j][2] + b0v) * gt;
                    o.y = (acc[i][j][3] + b1v) * gt;
                    *(float2*)&outp[(size_t)tok * HID + col] = o;
                }
            }
        }
    }

    // gemm1 tiles signal completion (release)
    if (IS_FC1) {
        __threadfence();
        __syncthreads();
        if (threadIdx.x == 0) atomicAdd(&g_done[e * G1_MT + mt], 1);
    }
}

// ---------------- fused gemm1+gemm2 launch ----------------
__global__ __launch_bounds__(128, 2) void moe_gemm_fused(const float* __restrict__ fc1_w,
                                                         const float* __restrict__ fc1_b,
                                                         const float* __restrict__ fc2_w,
                                                         const float* __restrict__ fc2_b,
                                                         float* __restrict__ outp) {
    int bid = blockIdx.x;
    if (bid < G1_TILES) {
        int e  = bid >> 10;
        int r  = bid & 1023;
        int mt = r >> 5;
        int nt = r & 31;
        gemm_tile<HID, true>(fc1_w, fc1_b, nullptr, e, mt, nt);
    } else {
        int b2 = bid - G1_TILES;
        int e  = b2 >> 8;
        int r  = b2 & 255;
        int mt = r >> 3;
        int nt = r & 7;
        gemm_tile<FFN, false>(fc2_w, fc2_b, outp, e, mt, nt);
    }
}

// ---------------- launch ----------------
extern "C" void kernel_launch(void* const* d_in, const int* in_sizes, int n_in,
                              void* d_out, int out_size) {
    const float* x        = (const float*)d_in[0];
    const float* router_w = (const float*)d_in[1];
    const float* fc1_w    = (const float*)d_in[2];
    const float* fc1_b    = (const float*)d_in[3];
    const float* fc2_w    = (const float*)d_in[4];
    const float* fc2_b    = (const float*)d_in[5];
    float* out = (float*)d_out;

    cudaFuncSetAttribute(moe_gemm_fused, cudaFuncAttributeMaxDynamicSharedMemorySize, SMEM_BYTES);

    router_kernel<<<TOK / 8, 256>>>(x, router_w);
    prefix_kernel<<<1, 256>>>(out, out_size);
    gather_kernel<<<TOK, 256>>>(x);

    moe_gemm_fused<<<G1_TILES + G2_TILES, 128, SMEM_BYTES>>>(fc1_w, fc1_b, fc2_w, fc2_b, out);
}